// round 17
// baseline (speedup 1.0000x reference)
#include <cuda_runtime.h>
#include <cuda_fp16.h>
#include <cstdint>

// GraphSAGE 2-layer encoder, gather-before-GEMM form (linearity):
//   m[i] = sum_{j in N(i)} h[j]                   (fp16 gather, raw sums)
//   out  = [inv*m | h] @ [Wl; Wr] + b             (single K=128 HMMA GEMM;
//                                                  inv folded into A-tile load)
// Edge lists padded to multiples of 4 (dummy zero row). Gather: 16-edge main
// loop (pair-tree) + <=3 remainder 4-blocks. Minimal padding waste.

#define NMAX 100000
#define EMAX 1600000
#define EPAD (EMAX + 4 * NMAX)
#define F 64
#define TSB 72    // B-tile row stride (halves)
#define TSA 136   // A-tile row stride (halves), 272B -> conflict-free ldsm

// +16 rows: row n (dummy) stays zero forever (BSS zero-init, never written)
__device__ __align__(16) __half g_xh[(NMAX + 16) * F];  // fp16 copy of x / layer input
__device__ __align__(16) __half g_h [(NMAX + 16) * F];  // layer-1 output
__device__ __align__(16) __half g_m [NMAX * F];         // aggregated sums (reused)
__device__ float g_invdeg[NMAX];
__device__ int   g_cnt[NMAX];        // zero-init at load; re-zeroed by last kernel
__device__ int   g_rowptr[NMAX];
__device__ int   g_rowend[NMAX];     // rowptr + padded count (mult of 4)
__device__ int   g_pos[EMAX];
__device__ int   g_col[EPAD];
__device__ int   g_ctr;              // chunk-base counter (re-zeroed by last kernel)

// ---------------------------------------------------------------- MMA bits
__device__ __forceinline__ unsigned smem_u32(const void* p) {
    return (unsigned)__cvta_generic_to_shared(p);
}
__device__ __forceinline__ void ldsm_x4(unsigned& a0, unsigned& a1,
                                        unsigned& a2, unsigned& a3, unsigned addr) {
    asm volatile("ldmatrix.sync.aligned.m8n8.x4.shared.b16 {%0,%1,%2,%3}, [%4];"
                 : "=r"(a0), "=r"(a1), "=r"(a2), "=r"(a3) : "r"(addr));
}
__device__ __forceinline__ void ldsm_x2t(unsigned& b0, unsigned& b1, unsigned addr) {
    asm volatile("ldmatrix.sync.aligned.m8n8.x2.trans.shared.b16 {%0,%1}, [%2];"
                 : "=r"(b0), "=r"(b1) : "r"(addr));
}
__device__ __forceinline__ void mma16816(float* d, unsigned a0, unsigned a1,
                                         unsigned a2, unsigned a3,
                                         unsigned b0, unsigned b1) {
    asm volatile("mma.sync.aligned.m16n8k16.row.col.f32.f16.f16.f32 "
                 "{%0,%1,%2,%3}, {%4,%5,%6,%7}, {%8,%9}, {%0,%1,%2,%3};"
                 : "+f"(d[0]), "+f"(d[1]), "+f"(d[2]), "+f"(d[3])
                 : "r"(a0), "r"(a1), "r"(a2), "r"(a3), "r"(b0), "r"(b1));
}

// Warp-cooperative gather over a range padded to a multiple of 4.
// lane = (g = l>>3 edge subgroup, s = l&7 dim chunk). Main loop: 16 edges
// per step (fp16 pair-tree, 4 loads/lane in flight). Remainder: <=3 steps
// of 4 edges (1 load/lane, direct cvt+add). Full sum on all lanes after shfl.
__device__ __forceinline__ void gather_row(const float4* __restrict__ Y,
                                           int i0, int e,
                                           int g, int s, float* acc) {
    #pragma unroll
    for (int d = 0; d < 8; ++d) acc[d] = 0.f;
    int e16 = i0 + ((e - i0) & ~15);
    for (int i = i0 + g; i < e16; i += 16) {
        float4 v0 = Y[g_col[i]      * 8 + s];
        float4 v1 = Y[g_col[i + 4]  * 8 + s];
        float4 v2 = Y[g_col[i + 8]  * 8 + s];
        float4 v3 = Y[g_col[i + 12] * 8 + s];
        __half2* h0 = (__half2*)&v0;
        __half2* h1 = (__half2*)&v1;
        __half2* h2 = (__half2*)&v2;
        __half2* h3 = (__half2*)&v3;
        #pragma unroll
        for (int k = 0; k < 4; ++k) {
            __half2 t = __hadd2(__hadd2(h0[k], h1[k]), __hadd2(h2[k], h3[k]));
            float2 f = __half22float2(t);
            acc[2 * k]     += f.x;
            acc[2 * k + 1] += f.y;
        }
    }
    for (int i = e16 + g; i < e; i += 4) {      // <=3 iterations
        float4 v = Y[g_col[i] * 8 + s];
        __half2* h = (__half2*)&v;
        #pragma unroll
        for (int k = 0; k < 4; ++k) {
            float2 f = __half22float2(h[k]);
            acc[2 * k]     += f.x;
            acc[2 * k + 1] += f.y;
        }
    }
    __syncwarp();
    #pragma unroll
    for (int d = 0; d < 8; ++d) {
        acc[d] += __shfl_xor_sync(0xffffffffu, acc[d], 8);
        acc[d] += __shfl_xor_sync(0xffffffffu, acc[d], 16);
    }
}

// ------------------ fused histogram (CSR pass 1) + x -> fp16 conversion
__global__ __launch_bounds__(256) void k_histprep(const int* __restrict__ dst, int E, int HB,
                                                  const float* __restrict__ X, int n) {
    if (blockIdx.x < (unsigned)HB) {
        int t  = blockIdx.x * 256 + threadIdx.x;
        int e4 = t * 4;
        if (e4 >= E) return;
        if (((E & 3) == 0) && e4 + 3 < E) {
            int4 d4 = ((const int4*)dst)[t];
            g_pos[e4 + 0] = atomicAdd(&g_cnt[d4.x], 1);
            g_pos[e4 + 1] = atomicAdd(&g_cnt[d4.y], 1);
            g_pos[e4 + 2] = atomicAdd(&g_cnt[d4.z], 1);
            g_pos[e4 + 3] = atomicAdd(&g_cnt[d4.w], 1);
        } else {
            int lim = min(e4 + 4, E);
            for (int e = e4; e < lim; ++e)
                g_pos[e] = atomicAdd(&g_cnt[dst[e]], 1);
        }
        return;
    }
    // convert 8 floats -> 8 halves per thread
    int idx  = ((int)blockIdx.x - HB) * 256 + threadIdx.x;
    int base = idx * 8;
    if (base < n * 64) {
        float4 a = *(const float4*)&X[base];
        float4 b = *(const float4*)&X[base + 4];
        __half2 hh[4];
        hh[0] = __floats2half2_rn(a.x, a.y);
        hh[1] = __floats2half2_rn(a.z, a.w);
        hh[2] = __floats2half2_rn(b.x, b.y);
        hh[3] = __floats2half2_rn(b.z, b.w);
        *(float4*)&g_xh[base] = *(float4*)hh;
    }
}

// single-pass CSR scan over counts padded to mult of 4; fills padding slots.
__global__ void k_scan(int n) {
    __shared__ int sh[1024];
    __shared__ int base_sh;
    int tid = threadIdx.x;
    int i = blockIdx.x * 1024 + tid;
    int v  = (i < n) ? g_cnt[i] : 0;
    int pc = (v + 3) & ~3;               // padded count (multiple of 4)
    sh[tid] = pc;
    __syncthreads();
    #pragma unroll
    for (int off = 1; off < 1024; off <<= 1) {
        int t = (tid >= off) ? sh[tid - off] : 0;
        __syncthreads();
        sh[tid] += t;
        __syncthreads();
    }
    if (tid == 1023) base_sh = atomicAdd(&g_ctr, sh[1023]);
    __syncthreads();
    if (i < n) {
        int rp = base_sh + sh[tid] - pc;
        g_rowptr[i] = rp;
        g_rowend[i] = rp + pc;
        g_invdeg[i] = 1.0f / (float)max(v, 1);
        for (int p = v; p < pc; ++p) g_col[rp + p] = n;   // dummy zero row
    }
}

// atomic-free scatter, 4 edges/thread
__global__ void k_scatter(const int* __restrict__ src, const int* __restrict__ dst, int E) {
    int t  = blockIdx.x * blockDim.x + threadIdx.x;
    int e4 = t * 4;
    if (e4 >= E) return;
    if (((E & 3) == 0) && e4 + 3 < E) {
        int4 d4 = ((const int4*)dst)[t];
        int4 p4 = ((const int4*)g_pos)[t];
        int4 s4 = ((const int4*)src)[t];
        g_col[g_rowptr[d4.x] + p4.x] = s4.x;
        g_col[g_rowptr[d4.y] + p4.y] = s4.y;
        g_col[g_rowptr[d4.z] + p4.z] = s4.z;
        g_col[g_rowptr[d4.w] + p4.w] = s4.w;
    } else {
        int lim = min(e4 + 4, E);
        for (int e = e4; e < lim; ++e)
            g_col[g_rowptr[dst[e]] + g_pos[e]] = src[e];
    }
}

// --------------------------- aggregate: m[i] = sum rows of (layer? h : xh)
// raw sums only (inv applied in gemm)
__global__ __launch_bounds__(256, 8) void k_agg(int layer, int n) {
    int tid  = threadIdx.x;
    int lane = tid & 31, w = tid >> 5;
    int node = blockIdx.x * 8 + w;
    int g = lane >> 3, s = lane & 7;
    if (node >= n) return;

    const float4* Y = (const float4*)(layer ? g_h : g_xh);
    float acc[8];
    gather_row(Y, g_rowptr[node], g_rowend[node], g, s, acc);

    if (g == 0) {
        __half2 hh[4];
        hh[0] = __floats2half2_rn(acc[0], acc[1]);
        hh[1] = __floats2half2_rn(acc[2], acc[3]);
        hh[2] = __floats2half2_rn(acc[4], acc[5]);
        hh[3] = __floats2half2_rn(acc[6], acc[7]);
        *(float4*)&g_m[node * 64 + s * 8] = *(float4*)hh;
    }
}

// ------------- concat GEMM: out = [inv*m | Yin] @ [Wl; Wr] + b  (K = 128)
// layer 0: Yin = xh, out -> g_h (relu, fp16). layer 1: Yin = h, out -> Og (fp32).
__global__ __launch_bounds__(256) void k_gemm(const float* __restrict__ Wl,
                                              const float* __restrict__ Wr,
                                              const float* __restrict__ B,
                                              float* __restrict__ Og,
                                              int layer, int n) {
    __shared__ __half xs[64 * TSA];
    __shared__ __half ws[128 * TSB];
    __shared__ float  bs[64];

    int tid  = threadIdx.x;
    int row0 = blockIdx.x * 64;

    // B tile: rows 0-63 = Wl, rows 64-127 = Wr  (row-major [64,64] each)
    for (int t = tid; t < 2048; t += 256) {
        int r = t >> 4, c4 = (t & 15) << 2;
        const float* Wsrc = (r < 64) ? &Wl[r * 64 + c4] : &Wr[(r - 64) * 64 + c4];
        float4 v = *(const float4*)Wsrc;
        *(__half2*)&ws[r * TSB + c4]     = __floats2half2_rn(v.x, v.y);
        *(__half2*)&ws[r * TSB + c4 + 2] = __floats2half2_rn(v.z, v.w);
    }
    // A tile: cols 0-63 = inv*m, cols 64-127 = Yin (both fp16)
    const __half* Yin = layer ? g_h : g_xh;
    for (int t = tid; t < 1024; t += 256) {
        int r = t >> 4, cc = t & 15;
        int gr = row0 + r;
        float4 v = make_float4(0.f, 0.f, 0.f, 0.f);
        if (gr < n) {
            if (cc < 8) {
                v = *(const float4*)&g_m[gr * 64 + cc * 8];
                __half2 inv2 = __half2half2(__float2half_rn(g_invdeg[gr]));
                __half2* hv = (__half2*)&v;
                hv[0] = __hmul2(hv[0], inv2);
                hv[1] = __hmul2(hv[1], inv2);
                hv[2] = __hmul2(hv[2], inv2);
                hv[3] = __hmul2(hv[3], inv2);
            } else {
                v = *(const float4*)&Yin[gr * 64 + (cc - 8) * 8];
            }
        }
        *(float4*)&xs[r * TSA + cc * 8] = v;
    }
    if (tid < 64) bs[tid] = B[tid];
    // cleanup (last kernel in chain when layer==1)
    if (layer && tid < 64) {
        int nn = row0 + tid;
        if (nn < n) g_cnt[nn] = 0;
    }
    if (layer && blockIdx.x == 0 && tid == 0) g_ctr = 0;
    __syncthreads();

    int w = tid >> 5, l = tid & 31;
    int m0 = (w & 3) * 16;
    int nb = (w >> 2) * 32;

    float acc[4][4];
    #pragma unroll
    for (int j = 0; j < 4; ++j)
        #pragma unroll
        for (int q = 0; q < 4; ++q) acc[j][q] = 0.f;

    int ag = l >> 3, ar = l & 7;
    int arow = m0 + (ag & 1) * 8 + ar;
    int acol = (ag >> 1) * 8;
    int br   = (l & 7) + ((l >> 3) & 1) * 8;

    #pragma unroll
    for (int kc = 0; kc < 8; ++kc) {
        int k0 = kc * 16;
        unsigned a0, a1, a2, a3;
        ldsm_x4(a0, a1, a2, a3, smem_u32(&xs[arow * TSA + k0 + acol]));
        #pragma unroll
        for (int j = 0; j < 4; ++j) {
            unsigned b0, b1;
            ldsm_x2t(b0, b1, smem_u32(&ws[(k0 + br) * TSB + nb + j * 8]));
            mma16816(acc[j], a0, a1, a2, a3, b0, b1);
        }
    }

    int tr = l >> 2, tc = (l & 3) * 2;
    #pragma unroll
    for (int j = 0; j < 4; ++j) {
        int gc = nb + j * 8 + tc;
        float bx = bs[gc], by = bs[gc + 1];
        #pragma unroll
        for (int h = 0; h < 2; ++h) {
            int gr = row0 + m0 + tr + h * 8;
            if (gr < n) {
                float vx = acc[j][h * 2]     + bx;
                float vy = acc[j][h * 2 + 1] + by;
                if (layer == 0) {
                    *(__half2*)&g_h[gr * 64 + gc] =
                        __floats2half2_rn(fmaxf(vx, 0.f), fmaxf(vy, 0.f));
                } else {
                    *(float2*)&Og[gr * 64 + gc] = make_float2(vx, vy);
                }
            }
        }
    }
}

// ------------------------------------------------------------------- launch
extern "C" void kernel_launch(void* const* d_in, const int* in_sizes, int n_in,
                              void* d_out, int out_size) {
    const float* x   = (const float*)d_in[0];
    const int*   ei  = (const int*)d_in[1];
    const float* w1l = (const float*)d_in[2];
    const float* b1l = (const float*)d_in[3];
    const float* w1r = (const float*)d_in[4];
    const float* w2l = (const float*)d_in[5];
    const float* b2l = (const float*)d_in[6];
    const float* w2r = (const float*)d_in[7];
    float* out = (float*)d_out;

    int n = in_sizes[0] / F;
    int E = in_sizes[1] / 2;
    const int* src = ei;
    const int* dst = ei + E;

    int HB = (E + 1023) / 1024;              // hist blocks (4 edges/thread)
    int CB = (n * 8 + 255) / 256;            // convert blocks (8 floats/thread)
    int GB = (n + 63) / 64;                  // gemm blocks

    k_histprep<<<HB + CB, 256>>>(dst, E, HB, x, n);
    k_scan    <<<(n + 1023) / 1024, 1024>>>(n);
    k_scatter <<<(E / 4 + 255) / 256, 256>>>(src, dst, E);

    k_agg <<<(n + 7) / 8, 256>>>(0, n);                      // m = sum(xh)
    k_gemm<<<GB, 256>>>(w1l, w1r, b1l, nullptr, 0, n);       // h = relu([inv*m|xh]@W1+b1)
    k_agg <<<(n + 7) / 8, 256>>>(1, n);                      // m = sum(h)
    k_gemm<<<GB, 256>>>(w2l, w2r, b2l, out, 1, n);           // out = [inv*m|h]@W2+b2
}